// round 11
// baseline (speedup 1.0000x reference)
#include <cuda_runtime.h>
#include <cstdint>

#define BB 256
#define TT 199
#define QQ 1000
#define NROW (BB * TT)               // 50,944
#define NEL  ((size_t)NROW * QQ)     // 50,944,000

// Packed per-batch accumulators:
//   bits[63:56] arrival count (<=199)
//   bits[55:48] masked-row count (<=199)
//   bits[47:0]  bce sum, fixed-point * 2^20 (max ~2.1e13 < 2^48, no carry)
// Zero at load; reset by their last user each launch (plain store — the next
// graph replay is stream-ordered after this kernel, so visibility is safe).
__device__ unsigned long long g_pack[BB];
// Global level: bits[63:48] batch arrivals (<=256), bits[47:0] loss * 2^32.
__device__ unsigned long long g_final;

// One block per (b, t) row. Proven 82%-DRAM body; epilogue = ONE packed
// atomic (data-carrying ticket, fenceless).
__global__ __launch_bounds__(256) void row_kernel(
    const float* __restrict__ pred,    // (B, T, Q)
    const float* __restrict__ batch,   // (B, T+1, Q)
    float* __restrict__ out)
{
    const int t   = blockIdx.x;
    const int b   = blockIdx.y;
    const int tid = threadIdx.x;
    const int lane = tid & 31;
    const int wid  = tid >> 5;

    const size_t row = (size_t)b * TT + t;
    const float* __restrict__ gt_row = batch + ((size_t)b * (TT + 1) + (t + 1)) * QQ;
    const float* __restrict__ p_row  = pred + row * QQ;

    __shared__ int   s_w[8];
    __shared__ float s_red[8];

    // ---- all 8 loads up front, unconditionally (max MLP) ----
    float g[4], p[4];
    #pragma unroll
    for (int k = 0; k < 4; k++) {
        int q = tid + 256 * k;
        bool valid = (k < 3) || (tid < QQ - 768);   // q < 1000
        g[k] = valid ? gt_row[q] : 0.0f;
        p[k] = valid ? p_row[q]  : 0.0f;
    }

    // ---- block-wide any(g == 1) ----
    int anyv = (g[0] == 1.0f) | (g[1] == 1.0f) | (g[2] == 1.0f) | (g[3] == 1.0f);
    unsigned wany = __ballot_sync(0xFFFFFFFFu, anyv);
    if (lane == 0) s_w[wid] = (wany != 0);
    __syncthreads();
    const int masked = s_w[0] | s_w[1] | s_w[2] | s_w[3] |
                       s_w[4] | s_w[5] | s_w[6] | s_w[7];
    const float fm = masked ? 1.0f : 0.0f;

    float* __restrict__ out_pred = out + 1 + row * QQ;
    float* __restrict__ out_gt   = out + 1 + NEL + row * QQ;

    float lsum = 0.0f;   // +(g*log p + (1-g)*log(1-p)); bce = -lsum
    #pragma unroll
    for (int k = 0; k < 4; k++) {
        int q = tid + 256 * k;
        bool valid = (k < 3) || (tid < QQ - 768);
        float pp = p[k], gg = g[k];
        float lp = fmaxf(__logf(pp),        -100.0f);
        float l1 = fmaxf(__logf(1.0f - pp), -100.0f);
        lsum += gg * lp + (1.0f - gg) * l1;
        if (valid) {
            out_pred[q] = pp * fm;
            out_gt[q]   = gg * fm;
        }
    }

    // ---- block reduction of lsum ----
    #pragma unroll
    for (int off = 16; off > 0; off >>= 1)
        lsum += __shfl_down_sync(0xFFFFFFFFu, lsum, off);
    if (lane == 0) s_red[wid] = lsum;
    __syncthreads();
    if (tid < 32) {
        float v = (tid < 8) ? s_red[tid] : 0.0f;
        #pragma unroll
        for (int off = 4; off > 0; off >>= 1)
            v += __shfl_down_sync(0xFFFFFFFFu, v, off);

        if (tid == 0) {
            out[1 + 2 * NEL + row] = fm;   // row_mask as float 0/1

            const double bce = (double)(fm * (-v));   // >= 0
            unsigned long long contrib =
                (1ull << 56)
                | (masked ? (1ull << 48) : 0ull)
                | (unsigned long long)(bce * 1048576.0 + 0.5);   // 2^20

            unsigned long long old = atomicAdd(&g_pack[b], contrib);
            if ((old >> 56) == (unsigned long long)(TT - 1)) {
                // Last arrival for batch b: full data is old + contrib.
                unsigned long long tot = old + contrib;
                const unsigned cnt = (unsigned)((tot >> 48) & 0xFFull);
                const double sum =
                    (double)(tot & 0xFFFFFFFFFFFFull) * (1.0 / 1048576.0);
                const double partial =
                    (cnt > 0) ? sum / ((double)cnt * (double)QQ) : 0.0;
                g_pack[b] = 0ull;           // reset for next replay

                unsigned long long c2 =
                    (1ull << 48)
                    | (unsigned long long)(partial * 4294967296.0 + 0.5); // 2^32
                unsigned long long old2 = atomicAdd(&g_final, c2);
                if ((old2 >> 48) == (unsigned long long)(BB - 1)) {
                    unsigned long long t2 = old2 + c2;
                    out[0] = (float)((double)(t2 & 0xFFFFFFFFFFFFull)
                                     * (1.0 / 4294967296.0));
                    g_final = 0ull;         // reset for next replay
                }
            }
        }
    }
}

extern "C" void kernel_launch(void* const* d_in, const int* in_sizes, int n_in,
                              void* d_out, int out_size) {
    const float* pred  = (const float*)d_in[0];
    const float* batch = (const float*)d_in[1];
    float* out = (float*)d_out;

    dim3 grid(TT, BB);
    row_kernel<<<grid, 256>>>(pred, batch, out);
}